// round 3
// baseline (speedup 1.0000x reference)
#include <cuda_runtime.h>
#include <cstdint>

#define SEQ 2048
#define HID 2048
#define NH 32
#define NKV 8
#define HD 64
#define HALF 32
#define SCALE 0.125f

// ---------------- scratch ----------------
__device__ float g_Q[NH * SEQ * HD];
__device__ float g_K[NKV * SEQ * HD];
__device__ float g_V[NKV * SEQ * HD];
__device__ float g_AO[SEQ * NH * HD];
__device__ float g_invl[NH * SEQ];

// ---------------- helpers ----------------
__device__ __forceinline__ void split2(float x, float& hi, float& lo)
{
    uint32_t h, l;
    asm("cvt.rna.tf32.f32 %0, %1;" : "=r"(h) : "f"(x));
    hi = __uint_as_float(h);
    float r = x - hi;
    asm("cvt.rna.tf32.f32 %0, %1;" : "=r"(l) : "f"(r));
    lo = __uint_as_float(l);
}

__device__ __forceinline__ void mma_tf32(float* d, const uint32_t* a, const uint32_t* b)
{
    asm volatile(
        "mma.sync.aligned.m16n8k8.row.col.f32.tf32.tf32.f32 "
        "{%0,%1,%2,%3}, {%4,%5,%6,%7}, {%8,%9}, {%0,%1,%2,%3};\n"
        : "+f"(d[0]), "+f"(d[1]), "+f"(d[2]), "+f"(d[3])
        : "r"(a[0]), "r"(a[1]), "r"(a[2]), "r"(a[3]), "r"(b[0]), "r"(b[1]));
}

// exp2 on the FMA pipe: magic-number round + degree-5 minimax + exponent add.
// valid for |y| < ~120; relative error ~1e-7.
__device__ __forceinline__ float fast_exp2(float y)
{
    float t = y + 12582912.f;                // 1.5 * 2^23 : round-to-nearest int
    float f = y - (t - 12582912.f);          // f in [-0.5, 0.5]
    int   n = __float_as_int(t) << 23;       // n*2^23 (low bits of magic cancel)
    float p;
    p = 1.3390776e-3f;
    p = fmaf(p, f, 9.6182376e-3f);
    p = fmaf(p, f, 5.5503573e-2f);
    p = fmaf(p, f, 2.4022649e-1f);
    p = fmaf(p, f, 6.9314720e-1f);
    p = fmaf(p, f, 1.0f);
    return __int_as_float(__float_as_int(p) + n);
}

// ---------------- 3xTF32 GEMM, split-on-load ------------------------------
// Y = X[2048 x HID] @ W[HID x ldN]; 128x64 tiles, 256 thr, warp tile 32x32.
// dyn smem: Ahi 128*33 | Alo 128*33 | Bhi 32*65 | Blo 32*65  (50432 B)
#define GEMM_SMEM_FLOATS (4224 * 2 + 2080 * 2)
#define GEMM_SMEM_BYTES (GEMM_SMEM_FLOATS * 4)

__global__ void __launch_bounds__(256)
gemm_tf32_kernel(const float* __restrict__ X,
                 const float* __restrict__ W,
                 float* __restrict__ outp,
                 const float* __restrict__ cosT,
                 const float* __restrict__ sinT,
                 int nColTiles, int doRope, int headMajor)
{
    extern __shared__ float gsm[];
    float* Ahi = gsm;
    float* Alo = gsm + 4224;
    float* Bhi = gsm + 8448;
    float* Blo = gsm + 10528;

    const int tid = threadIdx.x;
    const int lane = tid & 31, wid = tid >> 5;
    const int wm = wid & 3, wn = wid >> 2;
    const int g = lane >> 2, q = lane & 3;
    const int row0 = blockIdx.x * 128;
    const int col0 = blockIdx.y * 64;
    const int ldN = nColTiles * 64;

    float acc[2][4][4];
#pragma unroll
    for (int mt = 0; mt < 2; mt++)
#pragma unroll
        for (int nt = 0; nt < 4; nt++)
#pragma unroll
            for (int i = 0; i < 4; i++) acc[mt][nt][i] = 0.f;

    for (int k0 = 0; k0 < HID; k0 += 32) {
#pragma unroll
        for (int e = 0; e < 4; e++) {
            int idx = tid + e * 256;
            int r = idx >> 3, c = (idx & 7) * 4;
            float4 v = *(const float4*)(X + (size_t)(row0 + r) * HID + k0 + c);
            float hi, lo;
            split2(v.x, hi, lo); Ahi[r * 33 + c + 0] = hi; Alo[r * 33 + c + 0] = lo;
            split2(v.y, hi, lo); Ahi[r * 33 + c + 1] = hi; Alo[r * 33 + c + 1] = lo;
            split2(v.z, hi, lo); Ahi[r * 33 + c + 2] = hi; Alo[r * 33 + c + 2] = lo;
            split2(v.w, hi, lo); Ahi[r * 33 + c + 3] = hi; Alo[r * 33 + c + 3] = lo;
        }
#pragma unroll
        for (int e = 0; e < 2; e++) {
            int idx = tid + e * 256;
            int r = idx >> 4, c = (idx & 15) * 4;
            float4 v = *(const float4*)(W + (size_t)(k0 + r) * ldN + col0 + c);
            float hi, lo;
            split2(v.x, hi, lo); Bhi[r * 65 + c + 0] = hi; Blo[r * 65 + c + 0] = lo;
            split2(v.y, hi, lo); Bhi[r * 65 + c + 1] = hi; Blo[r * 65 + c + 1] = lo;
            split2(v.z, hi, lo); Bhi[r * 65 + c + 2] = hi; Blo[r * 65 + c + 2] = lo;
            split2(v.w, hi, lo); Bhi[r * 65 + c + 3] = hi; Blo[r * 65 + c + 3] = lo;
        }
        __syncthreads();
#pragma unroll
        for (int ks = 0; ks < 32; ks += 8) {
            uint32_t ah[2][4], al[2][4];
#pragma unroll
            for (int mt = 0; mt < 2; mt++) {
                int r = wm * 32 + mt * 16;
                ah[mt][0] = __float_as_uint(Ahi[(r + g) * 33 + ks + q]);
                ah[mt][1] = __float_as_uint(Ahi[(r + g + 8) * 33 + ks + q]);
                ah[mt][2] = __float_as_uint(Ahi[(r + g) * 33 + ks + q + 4]);
                ah[mt][3] = __float_as_uint(Ahi[(r + g + 8) * 33 + ks + q + 4]);
                al[mt][0] = __float_as_uint(Alo[(r + g) * 33 + ks + q]);
                al[mt][1] = __float_as_uint(Alo[(r + g + 8) * 33 + ks + q]);
                al[mt][2] = __float_as_uint(Alo[(r + g) * 33 + ks + q + 4]);
                al[mt][3] = __float_as_uint(Alo[(r + g + 8) * 33 + ks + q + 4]);
            }
#pragma unroll
            for (int nt = 0; nt < 4; nt++) {
                int c = wn * 32 + nt * 8 + g;
                uint32_t bh[2], bl[2];
                bh[0] = __float_as_uint(Bhi[(ks + q) * 65 + c]);
                bh[1] = __float_as_uint(Bhi[(ks + q + 4) * 65 + c]);
                bl[0] = __float_as_uint(Blo[(ks + q) * 65 + c]);
                bl[1] = __float_as_uint(Blo[(ks + q + 4) * 65 + c]);
#pragma unroll
                for (int mt = 0; mt < 2; mt++) {
                    mma_tf32(acc[mt][nt], ah[mt], bh);
                    mma_tf32(acc[mt][nt], ah[mt], bl);
                    mma_tf32(acc[mt][nt], al[mt], bh);
                }
            }
        }
        __syncthreads();
    }

    // epilogue via smem (RoPE needs cross-column pairing)
    float* Outs = gsm;  // [128][65]
#pragma unroll
    for (int mt = 0; mt < 2; mt++)
#pragma unroll
        for (int nt = 0; nt < 4; nt++) {
            int r = wm * 32 + mt * 16 + g;
            int c = wn * 32 + nt * 8 + 2 * q;
            Outs[r * 65 + c]           = acc[mt][nt][0];
            Outs[r * 65 + c + 1]       = acc[mt][nt][1];
            Outs[(r + 8) * 65 + c]     = acc[mt][nt][2];
            Outs[(r + 8) * 65 + c + 1] = acc[mt][nt][3];
        }
    __syncthreads();

    for (int e = tid; e < 128 * 64; e += 256) {
        int r = e >> 6, d = e & 63;
        float val;
        if (doRope) {
            float cc = cosT[(size_t)(row0 + r) * HALF + (d & 31)];
            float ss = sinT[(size_t)(row0 + r) * HALF + (d & 31)];
            if (d < HALF) val = Outs[r * 65 + d] * cc - Outs[r * 65 + d + HALF] * ss;
            else          val = Outs[r * 65 + d] * cc + Outs[r * 65 + d - HALF] * ss;
        } else {
            val = Outs[r * 65 + d];
        }
        if (headMajor)
            outp[((size_t)blockIdx.y * SEQ + row0 + r) * HD + d] = val;
        else
            outp[(size_t)(row0 + r) * ldN + col0 + d] = val;
    }
}

// ---------------- finalize weights: normalize + zero upper region -----------
__global__ void finalize_weights_kernel(float* __restrict__ w,
                                        const float* __restrict__ invl)
{
    int row = blockIdx.x;
    int i = row & (SEQ - 1);
    float s = invl[row];
    int bound4 = (((i >> 6) + 1) << 6) >> 2;
    float4* p = (float4*)(w + (size_t)row * SEQ);
    for (int j4 = threadIdx.x; j4 < SEQ / 4; j4 += blockDim.x) {
        if (j4 < bound4) {
            float4 v = p[j4];
            v.x *= s; v.y *= s; v.z *= s; v.w *= s;
            p[j4] = v;
        } else {
            p[j4] = make_float4(0.f, 0.f, 0.f, 0.f);
        }
    }
}

// ---------------- attention: tf32 mma, one pass -----------------------------
// dyn smem floats: Qhi 4160 | Qlo 4160 | KVhi 4160 | KVlo 4160 | Phi 4160 |
//                  Plo 4160 | lpart 128 | invl 64   = 25152 floats (100608 B)
#define ATTN_SMEM_FLOATS (4160 * 6 + 128 + 64)
#define ATTN_SMEM_BYTES (ATTN_SMEM_FLOATS * 4)

__global__ void __launch_bounds__(256)
attn_kernel(const float* __restrict__ Qh,
            const float* __restrict__ Kh,
            const float* __restrict__ Vh,
            const float* __restrict__ sinks,
            float* wout,
            float* __restrict__ aout,
            float* __restrict__ invl_out)
{
    extern __shared__ float asm_[];
    float* Qhi  = asm_;
    float* Qlo  = asm_ + 4160;
    float* KVhi = asm_ + 8320;
    float* KVlo = asm_ + 12480;
    float* Phi  = asm_ + 16640;
    float* Plo  = asm_ + 20800;
    float* lpart = asm_ + 24960;   // [2][64]
    float* invls = asm_ + 25088;   // [64]

    const int qt = gridDim.x - 1 - blockIdx.x;   // heavy tiles first
    const int h  = blockIdx.y;
    const int kh = h >> 2;
    const int tid = threadIdx.x;
    const int lane = tid & 31, wid = tid >> 5;
    const int wm = wid & 3, wn = wid >> 2;
    const int g = lane >> 2, q = lane & 3;
    const int mrow = wm * 16;                     // warp row base (local)
    const float KEXP = SCALE * 1.44269504089f;    // scale * log2(e)

    // load + split Q tile
    {
        const float4* Qg = (const float4*)(Qh + ((size_t)h * SEQ + qt * 64) * HD);
#pragma unroll
        for (int e = 0; e < 4; e++) {
            int idx = tid + e * 256;
            int r = idx >> 4, c = (idx & 15) * 4;
            float4 v = Qg[idx];
            float hi, lo;
            split2(v.x, hi, lo); Qhi[r * 65 + c + 0] = hi; Qlo[r * 65 + c + 0] = lo;
            split2(v.y, hi, lo); Qhi[r * 65 + c + 1] = hi; Qlo[r * 65 + c + 1] = lo;
            split2(v.z, hi, lo); Qhi[r * 65 + c + 2] = hi; Qlo[r * 65 + c + 2] = lo;
            split2(v.w, hi, lo); Qhi[r * 65 + c + 3] = hi; Qlo[r * 65 + c + 3] = lo;
        }
    }

    float oacc[4][4];
#pragma unroll
    for (int nt = 0; nt < 4; nt++)
#pragma unroll
        for (int i = 0; i < 4; i++) oacc[nt][i] = 0.f;
    float lsumA = 0.f, lsumB = 0.f;
    __syncthreads();

    for (int kt = 0; kt <= qt; kt++) {
        // K tile transposed + split: KV[d][key]
        {
            const float4* Kg = (const float4*)(Kh + ((size_t)kh * SEQ + kt * 64) * HD);
#pragma unroll
            for (int e = 0; e < 4; e++) {
                int idx = tid + e * 256;
                int r = idx >> 4, c = (idx & 15) * 4;
                float4 v = Kg[idx];
                float hi, lo;
                split2(v.x, hi, lo); KVhi[(c + 0) * 65 + r] = hi; KVlo[(c + 0) * 65 + r] = lo;
                split2(v.y, hi, lo); KVhi[(c + 1) * 65 + r] = hi; KVlo[(c + 1) * 65 + r] = lo;
                split2(v.z, hi, lo); KVhi[(c + 2) * 65 + r] = hi; KVlo[(c + 2) * 65 + r] = lo;
                split2(v.w, hi, lo); KVhi[(c + 3) * 65 + r] = hi; KVlo[(c + 3) * 65 + r] = lo;
            }
        }
        __syncthreads();

        // S = Q @ K^T (3xTF32)
        float sacc[4][4];
#pragma unroll
        for (int nt = 0; nt < 4; nt++)
#pragma unroll
            for (int i = 0; i < 4; i++) sacc[nt][i] = 0.f;
#pragma unroll
        for (int ks = 0; ks < 64; ks += 8) {
            uint32_t ah[4], al[4];
            ah[0] = __float_as_uint(Qhi[(mrow + g) * 65 + ks + q]);
            ah[1] = __float_as_uint(Qhi[(mrow + g + 8) * 65 + ks + q]);
            ah[2] = __float_as_uint(Qhi[(mrow + g) * 65 + ks + q + 4]);
            ah[3] = __float_as_uint(Qhi[(mrow + g + 8) * 65 + ks + q + 4]);
            al[0] = __float_as_uint(Qlo[(mrow + g) * 65 + ks + q]);
            al[1] = __float_as_uint(Qlo[(mrow + g + 8) * 65 + ks + q]);
            al[2] = __float_as_uint(Qlo[(mrow + g) * 65 + ks + q + 4]);
            al[3] = __float_as_uint(Qlo[(mrow + g + 8) * 65 + ks + q + 4]);
#pragma unroll
            for (int nt = 0; nt < 4; nt++) {
                int c = wn * 32 + nt * 8 + g;
                uint32_t bh[2], bl[2];
                bh[0] = __float_as_uint(KVhi[(ks + q) * 65 + c]);
                bh[1] = __float_as_uint(KVhi[(ks + q + 4) * 65 + c]);
                bl[0] = __float_as_uint(KVlo[(ks + q) * 65 + c]);
                bl[1] = __float_as_uint(KVlo[(ks + q + 4) * 65 + c]);
                mma_tf32(sacc[nt], ah, bh);
                mma_tf32(sacc[nt], ah, bl);
                mma_tf32(sacc[nt], al, bh);
            }
        }

        // weights: exp2 on FMA pipe, causal mask on diagonal tile
        const int growA = qt * 64 + mrow + g;
        const int growB = growA + 8;
        const bool diag = (kt == qt);
#pragma unroll
        for (int nt = 0; nt < 4; nt++) {
            int lcol = wn * 32 + nt * 8 + 2 * q;
            int gcol = kt * 64 + lcol;
            float w0 = fast_exp2(sacc[nt][0] * KEXP);
            float w1 = fast_exp2(sacc[nt][1] * KEXP);
            float w2 = fast_exp2(sacc[nt][2] * KEXP);
            float w3 = fast_exp2(sacc[nt][3] * KEXP);
            if (diag) {
                if (gcol > growA)     w0 = 0.f;
                if (gcol + 1 > growA) w1 = 0.f;
                if (gcol > growB)     w2 = 0.f;
                if (gcol + 1 > growB) w3 = 0.f;
            }
            lsumA += w0 + w1;
            lsumB += w2 + w3;
            if (wout) {
                *((float2*)(wout + ((size_t)h * SEQ + growA) * SEQ + gcol)) = make_float2(w0, w1);
                *((float2*)(wout + ((size_t)h * SEQ + growB) * SEQ + gcol)) = make_float2(w2, w3);
            }
            float hi, lo;
            int ra = mrow + g, rb = mrow + g + 8;
            split2(w0, hi, lo); Phi[ra * 65 + lcol]     = hi; Plo[ra * 65 + lcol]     = lo;
            split2(w1, hi, lo); Phi[ra * 65 + lcol + 1] = hi; Plo[ra * 65 + lcol + 1] = lo;
            split2(w2, hi, lo); Phi[rb * 65 + lcol]     = hi; Plo[rb * 65 + lcol]     = lo;
            split2(w3, hi, lo); Phi[rb * 65 + lcol + 1] = hi; Plo[rb * 65 + lcol + 1] = lo;
        }
        __syncthreads();   // P written; K reads done

        // V tile (natural layout, overwrites KV)
        {
            const float4* Vg = (const float4*)(Vh + ((size_t)kh * SEQ + kt * 64) * HD);
#pragma unroll
            for (int e = 0; e < 4; e++) {
                int idx = tid + e * 256;
                int r = idx >> 4, c = (idx & 15) * 4;
                float4 v = Vg[idx];
                float hi, lo;
                split2(v.x, hi, lo); KVhi[r * 65 + c + 0] = hi; KVlo[r * 65 + c + 0] = lo;
                split2(v.y, hi, lo); KVhi[r * 65 + c + 1] = hi; KVlo[r * 65 + c + 1] = lo;
                split2(v.z, hi, lo); KVhi[r * 65 + c + 2] = hi; KVlo[r * 65 + c + 2] = lo;
                split2(v.w, hi, lo); KVhi[r * 65 + c + 3] = hi; KVlo[r * 65 + c + 3] = lo;
            }
        }
        __syncthreads();

        // O += P @ V (3xTF32)
#pragma unroll
        for (int ks = 0; ks < 64; ks += 8) {
            uint32_t ah[4], al[4];
            ah[0] = __float_as_uint(Phi[(mrow + g) * 65 + ks + q]);
            ah[1] = __float_as_uint(Phi[(mrow + g + 8) * 65 + ks + q]);
            ah[2] = __float_as_uint(Phi[(mrow + g) * 65 + ks + q + 4]);
            ah[3] = __float_as_uint(Phi[(mrow + g + 8) * 65 + ks + q + 4]);
            al[0] = __float_as_uint(Plo[(mrow + g) * 65 + ks + q]);
            al[1] = __float_as_uint(Plo[(mrow + g + 8) * 65 + ks + q]);
            al[2] = __float_as_uint(Plo[(mrow + g) * 65 + ks + q + 4]);
            al[3] = __float_as_uint(Plo[(mrow + g + 8) * 65 + ks + q + 4]);
#pragma unroll
            for (int nt = 0; nt < 4; nt++) {
                int c = wn * 32 + nt * 8 + g;
                uint32_t bh[2], bl[2];
                bh[0] = __float_as_uint(KVhi[(ks + q) * 65 + c]);
                bh[1] = __float_as_uint(KVhi[(ks + q + 4) * 65 + c]);
                bl[0] = __float_as_uint(KVlo[(ks + q) * 65 + c]);
                bl[1] = __float_as_uint(KVlo[(ks + q + 4) * 65 + c]);
                mma_tf32(oacc[nt], ah, bh);
                mma_tf32(oacc[nt], ah, bl);
                mma_tf32(oacc[nt], al, bh);
            }
        }
        __syncthreads();   // V reads done before next kt overwrite
    }

    // row sums: reduce over quad lanes, combine warp halves, add sink
    lsumA += __shfl_xor_sync(0xffffffffu, lsumA, 1);
    lsumA += __shfl_xor_sync(0xffffffffu, lsumA, 2);
    lsumB += __shfl_xor_sync(0xffffffffu, lsumB, 1);
    lsumB += __shfl_xor_sync(0xffffffffu, lsumB, 2);
    if (q == 0) {
        lpart[wn * 64 + mrow + g]     = lsumA;
        lpart[wn * 64 + mrow + g + 8] = lsumB;
    }
    __syncthreads();
    if (tid < 64) {
        float sk = __expf(sinks[h]);
        float iv = 1.f / (lpart[tid] + lpart[64 + tid] + sk);
        invls[tid] = iv;
        invl_out[(size_t)h * SEQ + qt * 64 + tid] = iv;
    }
    __syncthreads();

    const float ivA = invls[mrow + g];
    const float ivB = invls[mrow + g + 8];
    const int growA = qt * 64 + mrow + g;
#pragma unroll
    for (int nt = 0; nt < 4; nt++) {
        int col = wn * 32 + nt * 8 + 2 * q;
        *((float2*)(aout + (size_t)growA * (NH * HD) + h * HD + col)) =
            make_float2(oacc[nt][0] * ivA, oacc[nt][1] * ivA);
        *((float2*)(aout + (size_t)(growA + 8) * (NH * HD) + h * HD + col)) =
            make_float2(oacc[nt][2] * ivB, oacc[nt][3] * ivB);
    }
}

// ---------------------------------------------------------------------------
extern "C" void kernel_launch(void* const* d_in, const int* in_sizes, int n_in,
                              void* d_out, int out_size)
{
    const float* X     = (const float*)d_in[0];
    const float* cosT  = (const float*)d_in[1];
    const float* sinT  = (const float*)d_in[2];
    const float* Wq    = (const float*)d_in[4];
    const float* Wk    = (const float*)d_in[5];
    const float* Wv    = (const float*)d_in[6];
    const float* Wo    = (const float*)d_in[7];
    const float* sinks = (const float*)d_in[8];

    float* out = (float*)d_out;
    const size_t AO_ELEMS = (size_t)SEQ * HID;
    const size_t W_ELEMS  = (size_t)NH * SEQ * SEQ;
    float* wout = ((size_t)out_size >= AO_ELEMS + W_ELEMS) ? out + AO_ELEMS : nullptr;

    float *Qd, *Kd, *Vd, *AOd, *ILd;
    cudaGetSymbolAddress((void**)&Qd,  g_Q);
    cudaGetSymbolAddress((void**)&Kd,  g_K);
    cudaGetSymbolAddress((void**)&Vd,  g_V);
    cudaGetSymbolAddress((void**)&AOd, g_AO);
    cudaGetSymbolAddress((void**)&ILd, g_invl);

    cudaFuncSetAttribute(gemm_tf32_kernel,
                         cudaFuncAttributeMaxDynamicSharedMemorySize, GEMM_SMEM_BYTES);
    cudaFuncSetAttribute(attn_kernel,
                         cudaFuncAttributeMaxDynamicSharedMemorySize, ATTN_SMEM_BYTES);

    gemm_tf32_kernel<<<dim3(SEQ / 128, NH), 256, GEMM_SMEM_BYTES>>>(X, Wq, Qd, cosT, sinT, NH, 1, 1);
    gemm_tf32_kernel<<<dim3(SEQ / 128, NKV), 256, GEMM_SMEM_BYTES>>>(X, Wk, Kd, cosT, sinT, NKV, 1, 1);
    gemm_tf32_kernel<<<dim3(SEQ / 128, NKV), 256, GEMM_SMEM_BYTES>>>(X, Wv, Vd, cosT, sinT, NKV, 0, 1);

    attn_kernel<<<dim3(SEQ / 64, NH), 256, ATTN_SMEM_BYTES>>>(Qd, Kd, Vd, sinks,
                                                              wout, AOd, ILd);

    if (wout)
        finalize_weights_kernel<<<NH * SEQ, 256>>>(wout, ILd);

    gemm_tf32_kernel<<<dim3(SEQ / 128, HID / 64), 256, GEMM_SMEM_BYTES>>>(AOd, Wo, out, cosT, sinT,
                                                                          HID / 64, 0, 0);
}

// round 4
// speedup vs baseline: 2.5197x; 2.5197x over previous
#include <cuda_runtime.h>
#include <cstdint>

#define SEQ 2048
#define HID 2048
#define NH 32
#define NKV 8
#define HD 64
#define HALF 32
#define SCALE 0.125f

// ---------------- scratch ----------------
__device__ float g_Q[NH * SEQ * HD];
__device__ float g_K[NKV * SEQ * HD];
__device__ float g_V[NKV * SEQ * HD];
__device__ float g_AO[SEQ * NH * HD];
__device__ float g_invl[NH * SEQ];

// ---------------- helpers ----------------
// split x into bf16 hi + bf16 lo, packed 2-k-per-u32 (x0 -> lower half).
__device__ __forceinline__ void split_pack(float x0, float x1,
                                           uint32_t& hp, uint32_t& lp)
{
    asm("cvt.rn.bf16x2.f32 %0, %1, %2;" : "=r"(hp) : "f"(x1), "f"(x0));
    float h0 = __uint_as_float(hp << 16);
    float h1 = __uint_as_float(hp & 0xffff0000u);
    float l0 = x0 - h0;
    float l1 = x1 - h1;
    asm("cvt.rn.bf16x2.f32 %0, %1, %2;" : "=r"(lp) : "f"(l1), "f"(l0));
}

__device__ __forceinline__ void mma_bf16(float* d, const uint32_t* a, const uint32_t* b)
{
    asm volatile(
        "mma.sync.aligned.m16n8k16.row.col.f32.bf16.bf16.f32 "
        "{%0,%1,%2,%3}, {%4,%5,%6,%7}, {%8,%9}, {%0,%1,%2,%3};\n"
        : "+f"(d[0]), "+f"(d[1]), "+f"(d[2]), "+f"(d[3])
        : "r"(a[0]), "r"(a[1]), "r"(a[2]), "r"(a[3]), "r"(b[0]), "r"(b[1]));
}

// exp2 on the FMA pipe (no MUFU): |y| < ~120, rel err ~1e-7.
__device__ __forceinline__ float fast_exp2(float y)
{
    float t = y + 12582912.f;
    float f = y - (t - 12582912.f);
    int   n = __float_as_int(t) << 23;
    float p;
    p = 1.3390776e-3f;
    p = fmaf(p, f, 9.6182376e-3f);
    p = fmaf(p, f, 5.5503573e-2f);
    p = fmaf(p, f, 2.4022649e-1f);
    p = fmaf(p, f, 6.9314720e-1f);
    p = fmaf(p, f, 1.0f);
    return __int_as_float(__float_as_int(p) + n);
}

// ---------------- bf16x2-split GEMM: Y = X[2048 x HID] @ W[HID x ldN] ------
// 128x64 tiles, 256 thr (8 warps, wm 0..3 x wn 0..1), warp tile 32x32.
// smem u32: Ahi 128*20 | Alo 128*20 | Bhi 16*74 | Blo 16*74 = 7488 u32.
// epilogue reuses smem as float [128][65] = 8320 -> GEMM_SMEM = 33280 B.
#define GEMM_SMEM_BYTES 33280

__global__ void __launch_bounds__(256)
gemm_bf16_kernel(const float* __restrict__ X,
                 const float* __restrict__ W,
                 float* __restrict__ outp,
                 const float* __restrict__ cosT,
                 const float* __restrict__ sinT,
                 int nColTiles, int doRope, int headMajor)
{
    extern __shared__ uint32_t gsm[];
    uint32_t* Ahi = gsm;            // [128][20]
    uint32_t* Alo = gsm + 2560;
    uint32_t* Bhi = gsm + 5120;     // [16][74]
    uint32_t* Blo = gsm + 6304;

    const int tid = threadIdx.x;
    const int lane = tid & 31, wid = tid >> 5;
    const int wm = wid & 3, wn = wid >> 2;
    const int g = lane >> 2, q = lane & 3;
    const int row0 = blockIdx.x * 128;
    const int col0 = blockIdx.y * 64;
    const int ldN = nColTiles * 64;

    float acc[2][4][4];
#pragma unroll
    for (int mt = 0; mt < 2; mt++)
#pragma unroll
        for (int nt = 0; nt < 4; nt++)
#pragma unroll
            for (int i = 0; i < 4; i++) acc[mt][nt][i] = 0.f;

    for (int k0 = 0; k0 < HID; k0 += 32) {
        // A chunk: [128 rows][32 k] -> pairs along k
#pragma unroll
        for (int e = 0; e < 4; e++) {
            int idx = tid + e * 256;
            int r = idx >> 3, c4 = (idx & 7) * 4;
            float4 v = *(const float4*)(X + (size_t)(row0 + r) * HID + k0 + c4);
            uint32_t hp, lp;
            split_pack(v.x, v.y, hp, lp);
            Ahi[r * 20 + (c4 >> 1)] = hp; Alo[r * 20 + (c4 >> 1)] = lp;
            split_pack(v.z, v.w, hp, lp);
            Ahi[r * 20 + (c4 >> 1) + 1] = hp; Alo[r * 20 + (c4 >> 1) + 1] = lp;
        }
        // B chunk: [32 k][64 n] -> pairs along k (load 2 rows per thread)
        {
            int a = tid >> 4, c4 = (tid & 15) * 4;   // 256 units exactly
            const float* Wp = W + (size_t)(k0 + 2 * a) * ldN + col0 + c4;
            float4 v0 = *(const float4*)(Wp);
            float4 v1 = *(const float4*)(Wp + ldN);
            uint32_t hp, lp;
            split_pack(v0.x, v1.x, hp, lp); Bhi[a * 74 + c4 + 0] = hp; Blo[a * 74 + c4 + 0] = lp;
            split_pack(v0.y, v1.y, hp, lp); Bhi[a * 74 + c4 + 1] = hp; Blo[a * 74 + c4 + 1] = lp;
            split_pack(v0.z, v1.z, hp, lp); Bhi[a * 74 + c4 + 2] = hp; Blo[a * 74 + c4 + 2] = lp;
            split_pack(v0.w, v1.w, hp, lp); Bhi[a * 74 + c4 + 3] = hp; Blo[a * 74 + c4 + 3] = lp;
        }
        __syncthreads();

#pragma unroll
        for (int kb = 0; kb < 16; kb += 8) {
            uint32_t ah[2][4], al[2][4];
#pragma unroll
            for (int mt = 0; mt < 2; mt++) {
                int r = wm * 32 + mt * 16;
                ah[mt][0] = Ahi[(r + g) * 20 + kb + q];
                ah[mt][1] = Ahi[(r + g + 8) * 20 + kb + q];
                ah[mt][2] = Ahi[(r + g) * 20 + kb + q + 4];
                ah[mt][3] = Ahi[(r + g + 8) * 20 + kb + q + 4];
                al[mt][0] = Alo[(r + g) * 20 + kb + q];
                al[mt][1] = Alo[(r + g + 8) * 20 + kb + q];
                al[mt][2] = Alo[(r + g) * 20 + kb + q + 4];
                al[mt][3] = Alo[(r + g + 8) * 20 + kb + q + 4];
            }
#pragma unroll
            for (int nt = 0; nt < 4; nt++) {
                int c = wn * 32 + nt * 8 + g;
                uint32_t bh[2], bl[2];
                bh[0] = Bhi[(kb + q) * 74 + c];
                bh[1] = Bhi[(kb + q + 4) * 74 + c];
                bl[0] = Blo[(kb + q) * 74 + c];
                bl[1] = Blo[(kb + q + 4) * 74 + c];
#pragma unroll
                for (int mt = 0; mt < 2; mt++) {
                    mma_bf16(acc[mt][nt], ah[mt], bh);
                    mma_bf16(acc[mt][nt], ah[mt], bl);
                    mma_bf16(acc[mt][nt], al[mt], bh);
                }
            }
        }
        __syncthreads();
    }

    // epilogue via smem-as-float (RoPE needs cross-column pairing)
    float* Outs = (float*)gsm;   // [128][65]
#pragma unroll
    for (int mt = 0; mt < 2; mt++)
#pragma unroll
        for (int nt = 0; nt < 4; nt++) {
            int r = wm * 32 + mt * 16 + g;
            int c = wn * 32 + nt * 8 + 2 * q;
            Outs[r * 65 + c]           = acc[mt][nt][0];
            Outs[r * 65 + c + 1]       = acc[mt][nt][1];
            Outs[(r + 8) * 65 + c]     = acc[mt][nt][2];
            Outs[(r + 8) * 65 + c + 1] = acc[mt][nt][3];
        }
    __syncthreads();

    for (int e = tid; e < 128 * 64; e += 256) {
        int r = e >> 6, d = e & 63;
        float val;
        if (doRope) {
            float cc = cosT[(size_t)(row0 + r) * HALF + (d & 31)];
            float ss = sinT[(size_t)(row0 + r) * HALF + (d & 31)];
            if (d < HALF) val = Outs[r * 65 + d] * cc - Outs[r * 65 + d + HALF] * ss;
            else          val = Outs[r * 65 + d] * cc + Outs[r * 65 + d - HALF] * ss;
        } else {
            val = Outs[r * 65 + d];
        }
        if (headMajor)
            outp[((size_t)blockIdx.y * SEQ + row0 + r) * HD + d] = val;
        else
            outp[(size_t)(row0 + r) * ldN + col0 + d] = val;
    }
}

// ---------------- finalize weights: normalize + zero upper region -----------
__global__ void finalize_weights_kernel(float* __restrict__ w,
                                        const float* __restrict__ invl)
{
    int row = blockIdx.x;
    int i = row & (SEQ - 1);
    float s = invl[row];
    int bound4 = (((i >> 6) + 1) << 6) >> 2;
    float4* p = (float4*)(w + (size_t)row * SEQ);
    for (int j4 = threadIdx.x; j4 < SEQ / 4; j4 += blockDim.x) {
        if (j4 < bound4) {
            float4 v = p[j4];
            v.x *= s; v.y *= s; v.z *= s; v.w *= s;
            p[j4] = v;
        } else {
            p[j4] = make_float4(0.f, 0.f, 0.f, 0.f);
        }
    }
}

// ---------------- attention: bf16x2-split mma, one pass ---------------------
// smem u32 layout:
//  Qhi [64][36]=2304 | Qlo 2304 | Bhi 2368 | Blo 2368 (K: [kp32][74];
//  later V^T: [64][37]=2368) | Phi [kp32][74]=2368 | Plo 2368 |
//  lpart 128 f | invls 64 f   => 14272 u32 = 57088 B  (4 CTAs/SM)
#define ATTN_SMEM_BYTES (14272 * 4)

__global__ void __launch_bounds__(256)
attn_kernel(const float* __restrict__ Qh,
            const float* __restrict__ Kh,
            const float* __restrict__ Vh,
            const float* __restrict__ sinks,
            float* wout,
            float* __restrict__ aout,
            float* __restrict__ invl_out)
{
    extern __shared__ uint32_t asmem[];
    uint32_t* Qhi = asmem;            // [64][36]
    uint32_t* Qlo = asmem + 2304;
    uint32_t* Bhi = asmem + 4608;     // K: [32][74] ; V^T: [64][37]
    uint32_t* Blo = asmem + 6976;
    uint32_t* Phi = asmem + 9344;     // P^T: [32][74]
    uint32_t* Plo = asmem + 11712;
    float* lpart  = (float*)(asmem + 14080);  // [2][64]
    float* invls  = lpart + 128;              // [64]

    const int qt = gridDim.x - 1 - blockIdx.x;   // heavy tiles first
    const int h  = blockIdx.y;
    const int kh = h >> 2;
    const int tid = threadIdx.x;
    const int lane = tid & 31, wid = tid >> 5;
    const int wm = wid & 3, wn = wid >> 2;
    const int g = lane >> 2, q = lane & 3;
    const int mrow = wm * 16;
    const float KEXP = SCALE * 1.44269504089f;

    // ---- load + split Q tile: [64 rows][64 d], pairs along d ----
#pragma unroll
    for (int e = 0; e < 4; e++) {
        int idx = tid + e * 256;
        int r = idx >> 4, c4 = (idx & 15) * 4;
        float4 v = *((const float4*)(Qh + ((size_t)h * SEQ + qt * 64) * HD) + idx);
        uint32_t hp, lp;
        split_pack(v.x, v.y, hp, lp);
        Qhi[r * 36 + (c4 >> 1)] = hp;     Qlo[r * 36 + (c4 >> 1)] = lp;
        split_pack(v.z, v.w, hp, lp);
        Qhi[r * 36 + (c4 >> 1) + 1] = hp; Qlo[r * 36 + (c4 >> 1) + 1] = lp;
    }

    float oacc[4][4];
#pragma unroll
    for (int nt = 0; nt < 4; nt++)
#pragma unroll
        for (int i = 0; i < 4; i++) oacc[nt][i] = 0.f;
    float lsumA = 0.f, lsumB = 0.f;
    __syncthreads();

    for (int kt = 0; kt <= qt; kt++) {
        // ---- K tile -> B planes [d-pair][key], ld 74 ----
#pragma unroll
        for (int e = 0; e < 4; e++) {
            int idx = tid + e * 256;
            int r = idx >> 4, c4 = (idx & 15) * 4;
            float4 v = *((const float4*)(Kh + ((size_t)kh * SEQ + kt * 64) * HD) + idx);
            uint32_t hp, lp;
            split_pack(v.x, v.y, hp, lp);
            Bhi[(c4 >> 1) * 74 + r] = hp;       Blo[(c4 >> 1) * 74 + r] = lp;
            split_pack(v.z, v.w, hp, lp);
            Bhi[((c4 >> 1) + 1) * 74 + r] = hp; Blo[((c4 >> 1) + 1) * 74 + r] = lp;
        }
        __syncthreads();

        // ---- S = Q @ K^T (3-product bf16 split) ----
        float sacc[4][4];
#pragma unroll
        for (int nt = 0; nt < 4; nt++)
#pragma unroll
            for (int i = 0; i < 4; i++) sacc[nt][i] = 0.f;
#pragma unroll
        for (int kb = 0; kb < 32; kb += 8) {
            uint32_t ah[4], al[4];
            ah[0] = Qhi[(mrow + g) * 36 + kb + q];
            ah[1] = Qhi[(mrow + g + 8) * 36 + kb + q];
            ah[2] = Qhi[(mrow + g) * 36 + kb + q + 4];
            ah[3] = Qhi[(mrow + g + 8) * 36 + kb + q + 4];
            al[0] = Qlo[(mrow + g) * 36 + kb + q];
            al[1] = Qlo[(mrow + g + 8) * 36 + kb + q];
            al[2] = Qlo[(mrow + g) * 36 + kb + q + 4];
            al[3] = Qlo[(mrow + g + 8) * 36 + kb + q + 4];
#pragma unroll
            for (int nt = 0; nt < 4; nt++) {
                int c = wn * 32 + nt * 8 + g;
                uint32_t bh[2], bl[2];
                bh[0] = Bhi[(kb + q) * 74 + c];
                bh[1] = Bhi[(kb + q + 4) * 74 + c];
                bl[0] = Blo[(kb + q) * 74 + c];
                bl[1] = Blo[(kb + q + 4) * 74 + c];
                mma_bf16(sacc[nt], ah, bh);
                mma_bf16(sacc[nt], ah, bl);
                mma_bf16(sacc[nt], al, bh);
            }
        }

        // ---- weights: exp2 on FMA pipe, causal mask, store P^T + wout ----
        const int growA = qt * 64 + mrow + g;
        const int growB = growA + 8;
        const bool diag = (kt == qt);
#pragma unroll
        for (int nt = 0; nt < 4; nt++) {
            int lcol = wn * 32 + nt * 8 + 2 * q;
            int gcol = kt * 64 + lcol;
            float w0 = fast_exp2(sacc[nt][0] * KEXP);
            float w1 = fast_exp2(sacc[nt][1] * KEXP);
            float w2 = fast_exp2(sacc[nt][2] * KEXP);
            float w3 = fast_exp2(sacc[nt][3] * KEXP);
            if (diag) {
                if (gcol > growA)     w0 = 0.f;
                if (gcol + 1 > growA) w1 = 0.f;
                if (gcol > growB)     w2 = 0.f;
                if (gcol + 1 > growB) w3 = 0.f;
            }
            lsumA += w0 + w1;
            lsumB += w2 + w3;
            if (wout) {
                *((float2*)(wout + ((size_t)h * SEQ + growA) * SEQ + gcol)) = make_float2(w0, w1);
                *((float2*)(wout + ((size_t)h * SEQ + growB) * SEQ + gcol)) = make_float2(w2, w3);
            }
            // P^T planes [key-pair][query], ld 74: pair (lcol, lcol+1) along key
            uint32_t hp, lp;
            split_pack(w0, w1, hp, lp);
            Phi[(lcol >> 1) * 74 + mrow + g] = hp;
            Plo[(lcol >> 1) * 74 + mrow + g] = lp;
            split_pack(w2, w3, hp, lp);
            Phi[(lcol >> 1) * 74 + mrow + g + 8] = hp;
            Plo[(lcol >> 1) * 74 + mrow + g + 8] = lp;
        }
        __syncthreads();   // K reads done; P visible

        // ---- V tile -> V^T A-planes [d][key-pair], ld 37 (reuse K region) ----
#pragma unroll
        for (int e = 0; e < 2; e++) {
            int idx = tid + e * 256;
            int a = idx >> 4, c4 = (idx & 15) * 4;   // key pair a, d=c4..c4+3
            const float* Vp = Vh + ((size_t)kh * SEQ + kt * 64 + 2 * a) * HD + c4;
            float4 v0 = *(const float4*)(Vp);
            float4 v1 = *(const float4*)(Vp + HD);
            uint32_t hp, lp;
            split_pack(v0.x, v1.x, hp, lp); Bhi[(c4 + 0) * 37 + a] = hp; Blo[(c4 + 0) * 37 + a] = lp;
            split_pack(v0.y, v1.y, hp, lp); Bhi[(c4 + 1) * 37 + a] = hp; Blo[(c4 + 1) * 37 + a] = lp;
            split_pack(v0.z, v1.z, hp, lp); Bhi[(c4 + 2) * 37 + a] = hp; Blo[(c4 + 2) * 37 + a] = lp;
            split_pack(v0.w, v1.w, hp, lp); Bhi[(c4 + 3) * 37 + a] = hp; Blo[(c4 + 3) * 37 + a] = lp;
        }
        __syncthreads();

        // ---- O^T += V^T @ P^T : A = V^T [d][key], B = P^T [key][query] ----
#pragma unroll
        for (int kb = 0; kb < 32; kb += 8) {
            uint32_t ah[4], al[4];
            ah[0] = Bhi[(mrow + g) * 37 + kb + q];
            ah[1] = Bhi[(mrow + g + 8) * 37 + kb + q];
            ah[2] = Bhi[(mrow + g) * 37 + kb + q + 4];
            ah[3] = Bhi[(mrow + g + 8) * 37 + kb + q + 4];
            al[0] = Blo[(mrow + g) * 37 + kb + q];
            al[1] = Blo[(mrow + g + 8) * 37 + kb + q];
            al[2] = Blo[(mrow + g) * 37 + kb + q + 4];
            al[3] = Blo[(mrow + g + 8) * 37 + kb + q + 4];
#pragma unroll
            for (int nt = 0; nt < 4; nt++) {
                int c = wn * 32 + nt * 8 + g;
                uint32_t bh[2], bl[2];
                bh[0] = Phi[(kb + q) * 74 + c];
                bh[1] = Phi[(kb + q + 4) * 74 + c];
                bl[0] = Plo[(kb + q) * 74 + c];
                bl[1] = Plo[(kb + q + 4) * 74 + c];
                mma_bf16(oacc[nt], ah, bh);
                mma_bf16(oacc[nt], ah, bl);
                mma_bf16(oacc[nt], al, bh);
            }
        }
        __syncthreads();   // V/P reads done before next kt overwrite
    }

    // ---- row sums (queries) -> invl (with sink) ----
    lsumA += __shfl_xor_sync(0xffffffffu, lsumA, 1);
    lsumA += __shfl_xor_sync(0xffffffffu, lsumA, 2);
    lsumB += __shfl_xor_sync(0xffffffffu, lsumB, 1);
    lsumB += __shfl_xor_sync(0xffffffffu, lsumB, 2);
    if (q == 0) {
        lpart[wn * 64 + mrow + g]     = lsumA;
        lpart[wn * 64 + mrow + g + 8] = lsumB;
    }
    __syncthreads();
    if (tid < 64) {
        float sk = __expf(sinks[h]);
        float iv = 1.f / (lpart[tid] + lpart[64 + tid] + sk);
        invls[tid] = iv;
        invl_out[(size_t)h * SEQ + qt * 64 + tid] = iv;
    }
    __syncthreads();

    // ---- store O (transposed accumulator: rows=d, cols=query) ----
#pragma unroll
    for (int nt = 0; nt < 4; nt++) {
        int c0 = wn * 32 + nt * 8 + 2 * q;         // query (local)
        int d0 = mrow + g;                          // head dim
        float iv0 = invls[c0], iv1 = invls[c0 + 1];
        float* base0 = aout + (size_t)(qt * 64 + c0) * (NH * HD) + h * HD;
        float* base1 = aout + (size_t)(qt * 64 + c0 + 1) * (NH * HD) + h * HD;
        base0[d0]     = oacc[nt][0] * iv0;
        base1[d0]     = oacc[nt][1] * iv1;
        base0[d0 + 8] = oacc[nt][2] * iv0;
        base1[d0 + 8] = oacc[nt][3] * iv1;
    }
}

// ---------------------------------------------------------------------------
extern "C" void kernel_launch(void* const* d_in, const int* in_sizes, int n_in,
                              void* d_out, int out_size)
{
    const float* X     = (const float*)d_in[0];
    const float* cosT  = (const float*)d_in[1];
    const float* sinT  = (const float*)d_in[2];
    const float* Wq    = (const float*)d_in[4];
    const float* Wk    = (const float*)d_in[5];
    const float* Wv    = (const float*)d_in[6];
    const float* Wo    = (const float*)d_in[7];
    const float* sinks = (const float*)d_in[8];

    float* out = (float*)d_out;
    const size_t AO_ELEMS = (size_t)SEQ * HID;
    const size_t W_ELEMS  = (size_t)NH * SEQ * SEQ;
    float* wout = ((size_t)out_size >= AO_ELEMS + W_ELEMS) ? out + AO_ELEMS : nullptr;

    float *Qd, *Kd, *Vd, *AOd, *ILd;
    cudaGetSymbolAddress((void**)&Qd,  g_Q);
    cudaGetSymbolAddress((void**)&Kd,  g_K);
    cudaGetSymbolAddress((void**)&Vd,  g_V);
    cudaGetSymbolAddress((void**)&AOd, g_AO);
    cudaGetSymbolAddress((void**)&ILd, g_invl);

    cudaFuncSetAttribute(gemm_bf16_kernel,
                         cudaFuncAttributeMaxDynamicSharedMemorySize, GEMM_SMEM_BYTES);
    cudaFuncSetAttribute(attn_kernel,
                         cudaFuncAttributeMaxDynamicSharedMemorySize, ATTN_SMEM_BYTES);

    gemm_bf16_kernel<<<dim3(SEQ / 128, NH), 256, GEMM_SMEM_BYTES>>>(X, Wq, Qd, cosT, sinT, NH, 1, 1);
    gemm_bf16_kernel<<<dim3(SEQ / 128, NKV), 256, GEMM_SMEM_BYTES>>>(X, Wk, Kd, cosT, sinT, NKV, 1, 1);
    gemm_bf16_kernel<<<dim3(SEQ / 128, NKV), 256, GEMM_SMEM_BYTES>>>(X, Wv, Vd, cosT, sinT, NKV, 0, 1);

    attn_kernel<<<dim3(SEQ / 64, NH), 256, ATTN_SMEM_BYTES>>>(Qd, Kd, Vd, sinks,
                                                              wout, AOd, ILd);

    if (wout)
        finalize_weights_kernel<<<NH * SEQ, 256>>>(wout, ILd);

    gemm_bf16_kernel<<<dim3(SEQ / 128, HID / 64), 256, GEMM_SMEM_BYTES>>>(AOd, Wo, out, cosT, sinT,
                                                                          HID / 64, 0, 0);
}

// round 5
// speedup vs baseline: 2.7769x; 1.1021x over previous
#include <cuda_runtime.h>
#include <cstdint>

#define SEQ 2048
#define HID 2048
#define NH 32
#define NKV 8
#define HD 64
#define HALF 32
#define SCALE 0.125f

// ---------------- scratch (u32 packed bf16 hi/lo planes) ----------------
__device__ uint32_t g_Xhi[2048 * 1024];
__device__ uint32_t g_Xlo[2048 * 1024];
// W planes: Wq @0 (1024x2048) | Wk @2097152 (1024x512) | Wv @2621440 | Wo @3145728
#define WOFF_Q 0
#define WOFF_K 2097152
#define WOFF_V 2621440
#define WOFF_O 3145728
__device__ uint32_t g_Whi[5242880];
__device__ uint32_t g_Wlo[5242880];
__device__ uint32_t g_Qhi[32 * 2048 * 32];    // [h][s][dpair]
__device__ uint32_t g_Qlo[32 * 2048 * 32];
__device__ uint32_t g_Kthi[8 * 32 * 2048];    // [kh][dpair][s]
__device__ uint32_t g_Ktlo[8 * 32 * 2048];
__device__ uint32_t g_Vthi[8 * 64 * 1024];    // [kh][d][spair]
__device__ uint32_t g_Vtlo[8 * 64 * 1024];
__device__ float    g_AO[2048 * 2048];
__device__ uint32_t g_AOhi[2048 * 1024];
__device__ uint32_t g_AOlo[2048 * 1024];
__device__ float    g_invl[NH * SEQ];

// ---------------- helpers ----------------
__device__ __forceinline__ void split_pack(float x0, float x1,
                                           uint32_t& hp, uint32_t& lp)
{
    asm("cvt.rn.bf16x2.f32 %0, %1, %2;" : "=r"(hp) : "f"(x1), "f"(x0));
    float h0 = __uint_as_float(hp << 16);
    float h1 = __uint_as_float(hp & 0xffff0000u);
    float l0 = x0 - h0;
    float l1 = x1 - h1;
    asm("cvt.rn.bf16x2.f32 %0, %1, %2;" : "=r"(lp) : "f"(l1), "f"(l0));
}

__device__ __forceinline__ void mma_bf16(float* d, const uint32_t* a, const uint32_t* b)
{
    asm volatile(
        "mma.sync.aligned.m16n8k16.row.col.f32.bf16.bf16.f32 "
        "{%0,%1,%2,%3}, {%4,%5,%6,%7}, {%8,%9}, {%0,%1,%2,%3};\n"
        : "+f"(d[0]), "+f"(d[1]), "+f"(d[2]), "+f"(d[3])
        : "r"(a[0]), "r"(a[1]), "r"(a[2]), "r"(a[3]), "r"(b[0]), "r"(b[1]));
}

// exp2 on the FMA pipe (no MUFU)
__device__ __forceinline__ float fast_exp2(float y)
{
    float t = y + 12582912.f;
    float f = y - (t - 12582912.f);
    int   n = __float_as_int(t) << 23;
    float p;
    p = 1.3390776e-3f;
    p = fmaf(p, f, 9.6182376e-3f);
    p = fmaf(p, f, 5.5503573e-2f);
    p = fmaf(p, f, 2.4022649e-1f);
    p = fmaf(p, f, 6.9314720e-1f);
    p = fmaf(p, f, 1.0f);
    return __int_as_float(__float_as_int(p) + n);
}

// ---------------- pack kernels ----------------
// W [2048 k][N] f32 -> [1024 kp][N] u32 planes (pairs along k)
__global__ void pack_rows_kernel(const float* __restrict__ src,
                                 uint32_t* __restrict__ hi,
                                 uint32_t* __restrict__ lo, int N)
{
    int n = blockIdx.y * 256 + threadIdx.x;
    int kp = blockIdx.x;
    float x0 = src[(size_t)(2 * kp) * N + n];
    float x1 = src[(size_t)(2 * kp + 1) * N + n];
    uint32_t hp, lp;
    split_pack(x0, x1, hp, lp);
    hi[(size_t)kp * N + n] = hp;
    lo[(size_t)kp * N + n] = lp;
}

// X [M][K] f32 -> [M][K/2] u32 planes (pairs along columns)
__global__ void pack_cols_kernel(const float4* __restrict__ src,
                                 uint2* __restrict__ hi,
                                 uint2* __restrict__ lo)
{
    int idx = blockIdx.x * 256 + threadIdx.x;
    float4 v = src[idx];
    uint32_t h0, l0, h1, l1;
    split_pack(v.x, v.y, h0, l0);
    split_pack(v.z, v.w, h1, l1);
    hi[idx] = make_uint2(h0, h1);
    lo[idx] = make_uint2(l0, l1);
}

// ---------------- GEMM on packed planes -------------------------------------
// C[128 x TN] tile of X[2048 x 2048] @ W[2048 x ldB]; 256 thr, 8 warps.
// MODE: 0 = f32 out [row][2048]; 1 = Q planes (+RoPE); 2 = K^T planes (+RoPE);
//       3 = V^T planes.
template<int TN, int MODE>
__global__ void __launch_bounds__(256)
gemm_pk_kernel(const uint32_t* __restrict__ Ahi_g, const uint32_t* __restrict__ Alo_g,
               const uint32_t* __restrict__ Bhi_g, const uint32_t* __restrict__ Blo_g,
               int ldB,
               float* __restrict__ outF,
               uint32_t* __restrict__ Ohi_g, uint32_t* __restrict__ Olo_g,
               const float* __restrict__ cosT, const float* __restrict__ sinT)
{
    extern __shared__ uint32_t sm[];
    uint32_t* Ash = sm;                       // [128][20]
    uint32_t* Asl = sm + 2560;
    uint32_t* Bsh = sm + 5120;                // [16][TN] xor-swizzled
    uint32_t* Bsl = sm + 5120 + 16 * TN;

    const int tid = threadIdx.x;
    const int lane = tid & 31, wid = tid >> 5;
    const int wm = wid & 3, wn = wid >> 2;
    const int g = lane >> 2, q = lane & 3;
    const int row0 = blockIdx.x * 128;
    const int col0 = blockIdx.y * TN;
    constexpr int NT = TN / 16;

    float acc[2][NT][4];
#pragma unroll
    for (int mt = 0; mt < 2; mt++)
#pragma unroll
        for (int nt = 0; nt < NT; nt++)
#pragma unroll
            for (int i = 0; i < 4; i++) acc[mt][nt][i] = 0.f;

    for (int kp0 = 0; kp0 < 1024; kp0 += 16) {
        // A: 128 rows x 16 kp (uint4 x2 per thread per plane)
#pragma unroll
        for (int e = 0; e < 2; e++) {
            int idx = tid + e * 256;
            int r = idx >> 2, k4 = (idx & 3) * 4;
            size_t ga = (size_t)(row0 + r) * 1024 + kp0 + k4;
            *(uint4*)(Ash + r * 20 + k4) = *(const uint4*)(Ahi_g + ga);
            *(uint4*)(Asl + r * 20 + k4) = *(const uint4*)(Alo_g + ga);
        }
        // B: 16 kp x TN, xor swizzle (n ^ ((kp&3)<<3))
#pragma unroll
        for (int e = 0; e < (16 * TN) / 1024; e++) {
            int idx = tid + e * 256;
            int kp = idx / (TN / 4), n4 = (idx % (TN / 4)) * 4;
            int sw = n4 ^ ((kp & 3) << 3);
            size_t gb = (size_t)(kp0 + kp) * ldB + col0 + n4;
            *(uint4*)(Bsh + kp * TN + sw) = *(const uint4*)(Bhi_g + gb);
            *(uint4*)(Bsl + kp * TN + sw) = *(const uint4*)(Blo_g + gb);
        }
        __syncthreads();

#pragma unroll
        for (int kb = 0; kb < 16; kb += 8) {
            uint32_t ah[2][4], al[2][4];
#pragma unroll
            for (int mt = 0; mt < 2; mt++) {
                int r = wm * 32 + mt * 16;
                ah[mt][0] = Ash[(r + g) * 20 + kb + q];
                ah[mt][1] = Ash[(r + g + 8) * 20 + kb + q];
                ah[mt][2] = Ash[(r + g) * 20 + kb + q + 4];
                ah[mt][3] = Ash[(r + g + 8) * 20 + kb + q + 4];
                al[mt][0] = Asl[(r + g) * 20 + kb + q];
                al[mt][1] = Asl[(r + g + 8) * 20 + kb + q];
                al[mt][2] = Asl[(r + g) * 20 + kb + q + 4];
                al[mt][3] = Asl[(r + g + 8) * 20 + kb + q + 4];
            }
#pragma unroll
            for (int nt = 0; nt < NT; nt++) {
                int c = wn * (TN / 2) + nt * 8 + g;
                int sc = c ^ (q << 3);
                uint32_t bh[2], bl[2];
                bh[0] = Bsh[(kb + q) * TN + sc];
                bh[1] = Bsh[(kb + q + 4) * TN + sc];
                bl[0] = Bsl[(kb + q) * TN + sc];
                bl[1] = Bsl[(kb + q + 4) * TN + sc];
#pragma unroll
                for (int mt = 0; mt < 2; mt++) {
                    mma_bf16(acc[mt][nt], ah[mt], bh);
                    mma_bf16(acc[mt][nt], ah[mt], bl);
                    mma_bf16(acc[mt][nt], al[mt], bh);
                }
            }
        }
        __syncthreads();
    }

    // ---- epilogue: accumulators -> smem fp32, then mode-specific writer ----
    constexpr int OLD = TN + 4;
    float* Outs = (float*)sm;   // [128][OLD]
#pragma unroll
    for (int mt = 0; mt < 2; mt++)
#pragma unroll
        for (int nt = 0; nt < NT; nt++) {
            int r = wm * 32 + mt * 16 + g;
            int c = wn * (TN / 2) + nt * 8 + 2 * q;
            Outs[r * OLD + c]           = acc[mt][nt][0];
            Outs[r * OLD + c + 1]       = acc[mt][nt][1];
            Outs[(r + 8) * OLD + c]     = acc[mt][nt][2];
            Outs[(r + 8) * OLD + c + 1] = acc[mt][nt][3];
        }
    __syncthreads();

    if constexpr (MODE == 0) {
        for (int e = tid; e < 128 * (TN / 4); e += 256) {
            int r = e / (TN / 4), c4 = (e % (TN / 4)) * 4;
            float4 v = *(float4*)(Outs + r * OLD + c4);
            *(float4*)(outF + (size_t)(row0 + r) * 2048 + col0 + c4) = v;
        }
    } else if constexpr (MODE == 1) {     // Q: RoPE + pack pairs along d
        for (int e = tid; e < 128 * 64; e += 256) {
            int r = e >> 6, dp = e & 63;
            int cl = dp * 2;
            int s = row0 + r;
            int d0 = cl & 63;
            int h = (col0 + cl) >> 6;
            float o0 = Outs[r * OLD + cl], o1 = Outs[r * OLD + cl + 1];
            float c0 = cosT[s * 32 + (d0 & 31)], s0 = sinT[s * 32 + (d0 & 31)];
            float c1 = cosT[s * 32 + ((d0 + 1) & 31)], s1 = sinT[s * 32 + ((d0 + 1) & 31)];
            float v0, v1;
            if (d0 < 32) {
                v0 = o0 * c0 - Outs[r * OLD + cl + 32] * s0;
                v1 = o1 * c1 - Outs[r * OLD + cl + 33] * s1;
            } else {
                v0 = o0 * c0 + Outs[r * OLD + cl - 32] * s0;
                v1 = o1 * c1 + Outs[r * OLD + cl - 31] * s1;
            }
            uint32_t hp, lp;
            split_pack(v0, v1, hp, lp);
            size_t o = ((size_t)h * 2048 + s) * 32 + (d0 >> 1);
            Ohi_g[o] = hp; Olo_g[o] = lp;
        }
    } else if constexpr (MODE == 2) {     // K^T: RoPE + pack pairs along d
        int kh = blockIdx.y;
        for (int e = tid; e < 128 * 32; e += 256) {
            int sl = e & 127, dp = e >> 7;
            int d0 = 2 * dp;
            int s = row0 + sl;
            float o0 = Outs[sl * OLD + d0], o1 = Outs[sl * OLD + d0 + 1];
            float c0 = cosT[s * 32 + (d0 & 31)], s0 = sinT[s * 32 + (d0 & 31)];
            float c1 = cosT[s * 32 + ((d0 + 1) & 31)], s1 = sinT[s * 32 + ((d0 + 1) & 31)];
            float v0, v1;
            if (d0 < 32) {
                v0 = o0 * c0 - Outs[sl * OLD + d0 + 32] * s0;
                v1 = o1 * c1 - Outs[sl * OLD + d0 + 33] * s1;
            } else {
                v0 = o0 * c0 + Outs[sl * OLD + d0 - 32] * s0;
                v1 = o1 * c1 + Outs[sl * OLD + d0 - 31] * s1;
            }
            uint32_t hp, lp;
            split_pack(v0, v1, hp, lp);
            size_t o = ((size_t)kh * 32 + dp) * 2048 + s;
            Ohi_g[o] = hp; Olo_g[o] = lp;
        }
    } else {                              // MODE 3, V^T: pack pairs along s
        int kh = blockIdx.y;
        for (int e = tid; e < 64 * 64; e += 256) {
            int sp = e & 63, d = e >> 6;
            float v0 = Outs[(2 * sp) * OLD + d];
            float v1 = Outs[(2 * sp + 1) * OLD + d];
            uint32_t hp, lp;
            split_pack(v0, v1, hp, lp);
            size_t o = ((size_t)kh * 64 + d) * 1024 + (row0 >> 1) + sp;
            Ohi_g[o] = hp; Olo_g[o] = lp;
        }
    }
}

// ---------------- finalize weights ----------------
__global__ void finalize_weights_kernel(float* __restrict__ w,
                                        const float* __restrict__ invl)
{
    int row = blockIdx.x;
    int i = row & (SEQ - 1);
    float s = invl[row];
    int bound4 = (((i >> 6) + 1) << 6) >> 2;
    float4* p = (float4*)(w + (size_t)row * SEQ);
    for (int j4 = threadIdx.x; j4 < SEQ / 4; j4 += blockDim.x) {
        if (j4 < bound4) {
            float4 v = p[j4];
            v.x *= s; v.y *= s; v.z *= s; v.w *= s;
            p[j4] = v;
        } else {
            p[j4] = make_float4(0.f, 0.f, 0.f, 0.f);
        }
    }
}

// ---------------- attention on packed planes --------------------------------
// smem u32: Qsh 2304 | Qsl 2304 | KVh 2304 | KVl 2304 | Psh 2048 | Psl 2048 |
//           lpart 128f | invls 64f   => 13504 u32 = 54016 B
#define ATTN_SMEM_BYTES (13504 * 4)

__global__ void __launch_bounds__(256)
attn_kernel(const uint32_t* __restrict__ Qhi_g, const uint32_t* __restrict__ Qlo_g,
            const uint32_t* __restrict__ Khi_g, const uint32_t* __restrict__ Klo_g,
            const uint32_t* __restrict__ Vhi_g, const uint32_t* __restrict__ Vlo_g,
            const float* __restrict__ sinks,
            float* wout, float* __restrict__ aout, float* __restrict__ invl_out)
{
    extern __shared__ uint32_t asmem[];
    uint32_t* Qsh = asmem;            // [64][36]
    uint32_t* Qsl = asmem + 2304;
    uint32_t* KVh = asmem + 4608;     // K: [32][64] swz ; V: [64][36]
    uint32_t* KVl = asmem + 6912;
    uint32_t* Psh = asmem + 9216;     // P^T: [32][64] swz
    uint32_t* Psl = asmem + 11264;
    float* lpart  = (float*)(asmem + 13312);  // [2][64]
    float* invls  = lpart + 128;              // [64]

    const int qt = gridDim.x - 1 - blockIdx.x;   // heavy tiles first
    const int h  = blockIdx.y;
    const int kh = h >> 2;
    const int tid = threadIdx.x;
    const int lane = tid & 31, wid = tid >> 5;
    const int wm = wid & 3, wn = wid >> 2;
    const int g = lane >> 2, q = lane & 3;
    const int mrow = wm * 16;
    const float KEXP = SCALE * 1.44269504089f;

    // Q tile copy (packed planes, straight uint4 copies)
    {
        const uint32_t* Qbh = Qhi_g + ((size_t)h * 2048 + qt * 64) * 32;
        const uint32_t* Qbl = Qlo_g + ((size_t)h * 2048 + qt * 64) * 32;
#pragma unroll
        for (int e = 0; e < 2; e++) {
            int idx = tid + e * 256;
            int r = idx >> 3, c4 = (idx & 7) * 4;
            *(uint4*)(Qsh + r * 36 + c4) = *(const uint4*)(Qbh + r * 32 + c4);
            *(uint4*)(Qsl + r * 36 + c4) = *(const uint4*)(Qbl + r * 32 + c4);
        }
    }

    float oacc[4][4];
#pragma unroll
    for (int nt = 0; nt < 4; nt++)
#pragma unroll
        for (int i = 0; i < 4; i++) oacc[nt][i] = 0.f;
    float lsumA = 0.f, lsumB = 0.f;
    __syncthreads();

    for (int kt = 0; kt <= qt; kt++) {
        // ---- K^T tile copy [32 dp][64 s], xor swizzle ----
        {
            const uint32_t* Kbh = Khi_g + (size_t)kh * 32 * 2048 + kt * 64;
            const uint32_t* Kbl = Klo_g + (size_t)kh * 32 * 2048 + kt * 64;
#pragma unroll
            for (int e = 0; e < 2; e++) {
                int idx = tid + e * 256;
                int dp = idx >> 4, s4 = (idx & 15) * 4;
                int sw = s4 ^ ((dp & 3) << 3);
                *(uint4*)(KVh + dp * 64 + sw) = *(const uint4*)(Kbh + (size_t)dp * 2048 + s4);
                *(uint4*)(KVl + dp * 64 + sw) = *(const uint4*)(Kbl + (size_t)dp * 2048 + s4);
            }
        }
        __syncthreads();

        // ---- S = Q @ K^T ----
        float sacc[4][4];
#pragma unroll
        for (int nt = 0; nt < 4; nt++)
#pragma unroll
            for (int i = 0; i < 4; i++) sacc[nt][i] = 0.f;
#pragma unroll
        for (int kb = 0; kb < 32; kb += 8) {
            uint32_t ah[4], al[4];
            ah[0] = Qsh[(mrow + g) * 36 + kb + q];
            ah[1] = Qsh[(mrow + g + 8) * 36 + kb + q];
            ah[2] = Qsh[(mrow + g) * 36 + kb + q + 4];
            ah[3] = Qsh[(mrow + g + 8) * 36 + kb + q + 4];
            al[0] = Qsl[(mrow + g) * 36 + kb + q];
            al[1] = Qsl[(mrow + g + 8) * 36 + kb + q];
            al[2] = Qsl[(mrow + g) * 36 + kb + q + 4];
            al[3] = Qsl[(mrow + g + 8) * 36 + kb + q + 4];
#pragma unroll
            for (int nt = 0; nt < 4; nt++) {
                int c = wn * 32 + nt * 8 + g;
                int sc = c ^ (q << 3);
                uint32_t bh[2], bl[2];
                bh[0] = KVh[(kb + q) * 64 + sc];
                bh[1] = KVh[(kb + q + 4) * 64 + sc];
                bl[0] = KVl[(kb + q) * 64 + sc];
                bl[1] = KVl[(kb + q + 4) * 64 + sc];
                mma_bf16(sacc[nt], ah, bh);
                mma_bf16(sacc[nt], ah, bl);
                mma_bf16(sacc[nt], al, bh);
            }
        }

        // ---- exp + mask + store P^T (swizzled) + wout ----
        const int growA = qt * 64 + mrow + g;
        const int growB = growA + 8;
        const bool diag = (kt == qt);
#pragma unroll
        for (int nt = 0; nt < 4; nt++) {
            int lcol = wn * 32 + nt * 8 + 2 * q;
            int gcol = kt * 64 + lcol;
            float w0 = fast_exp2(sacc[nt][0] * KEXP);
            float w1 = fast_exp2(sacc[nt][1] * KEXP);
            float w2 = fast_exp2(sacc[nt][2] * KEXP);
            float w3 = fast_exp2(sacc[nt][3] * KEXP);
            if (diag) {
                if (gcol > growA)     w0 = 0.f;
                if (gcol + 1 > growA) w1 = 0.f;
                if (gcol > growB)     w2 = 0.f;
                if (gcol + 1 > growB) w3 = 0.f;
            }
            lsumA += w0 + w1;
            lsumB += w2 + w3;
            if (wout) {
                *((float2*)(wout + ((size_t)h * SEQ + growA) * SEQ + gcol)) = make_float2(w0, w1);
                *((float2*)(wout + ((size_t)h * SEQ + growB) * SEQ + gcol)) = make_float2(w2, w3);
            }
            int pr = lcol >> 1;                     // = wn*16 + nt*4 + q
            uint32_t hp, lp;
            split_pack(w0, w1, hp, lp);
            int swA = (mrow + g) ^ ((pr & 3) << 3);
            Psh[pr * 64 + swA] = hp; Psl[pr * 64 + swA] = lp;
            split_pack(w2, w3, hp, lp);
            int swB = (mrow + g + 8) ^ ((pr & 3) << 3);
            Psh[pr * 64 + swB] = hp; Psl[pr * 64 + swB] = lp;
        }
        __syncthreads();   // K reads done; P visible

        // ---- V^T tile copy [64 d][32 sp], ld 36 ----
        {
            const uint32_t* Vbh = Vhi_g + (size_t)kh * 64 * 1024 + kt * 32;
            const uint32_t* Vbl = Vlo_g + (size_t)kh * 64 * 1024 + kt * 32;
#pragma unroll
            for (int e = 0; e < 2; e++) {
                int idx = tid + e * 256;
                int d = idx >> 3, sp4 = (idx & 7) * 4;
                *(uint4*)(KVh + d * 36 + sp4) = *(const uint4*)(Vbh + (size_t)d * 1024 + sp4);
                *(uint4*)(KVl + d * 36 + sp4) = *(const uint4*)(Vbl + (size_t)d * 1024 + sp4);
            }
        }
        __syncthreads();

        // ---- O^T += V^T @ P^T ----
#pragma unroll
        for (int kb = 0; kb < 32; kb += 8) {
            uint32_t ah[4], al[4];
            ah[0] = KVh[(mrow + g) * 36 + kb + q];
            ah[1] = KVh[(mrow + g + 8) * 36 + kb + q];
            ah[2] = KVh[(mrow + g) * 36 + kb + q + 4];
            ah[3] = KVh[(mrow + g + 8) * 36 + kb + q + 4];
            al[0] = KVl[(mrow + g) * 36 + kb + q];
            al[1] = KVl[(mrow + g + 8) * 36 + kb + q];
            al[2] = KVl[(mrow + g) * 36 + kb + q + 4];
            al[3] = KVl[(mrow + g + 8) * 36 + kb + q + 4];
#pragma unroll
            for (int nt = 0; nt < 4; nt++) {
                int c = wn * 32 + nt * 8 + g;
                int sc = c ^ (q << 3);
                uint32_t bh[2], bl[2];
                bh[0] = Psh[(kb + q) * 64 + sc];
                bh[1] = Psh[(kb + q + 4) * 64 + sc];
                bl[0] = Psl[(kb + q) * 64 + sc];
                bl[1] = Psl[(kb + q + 4) * 64 + sc];
                mma_bf16(oacc[nt], ah, bh);
                mma_bf16(oacc[nt], ah, bl);
                mma_bf16(oacc[nt], al, bh);
            }
        }
        __syncthreads();   // V/P reads done before next kt overwrite
    }

    // ---- row sums -> invl (with sink) ----
    lsumA += __shfl_xor_sync(0xffffffffu, lsumA, 1);
    lsumA += __shfl_xor_sync(0xffffffffu, lsumA, 2);
    lsumB += __shfl_xor_sync(0xffffffffu, lsumB, 1);
    lsumB += __shfl_xor_sync(0xffffffffu, lsumB, 2);
    if (q == 0) {
        lpart[wn * 64 + mrow + g]     = lsumA;
        lpart[wn * 64 + mrow + g + 8] = lsumB;
    }
    __syncthreads();
    if (tid < 64) {
        float sk = __expf(sinks[h]);
        float iv = 1.f / (lpart[tid] + lpart[64 + tid] + sk);
        invls[tid] = iv;
        invl_out[(size_t)h * SEQ + qt * 64 + tid] = iv;
    }
    __syncthreads();

    // ---- store O (transposed accumulator: rows=d, cols=query) ----
#pragma unroll
    for (int nt = 0; nt < 4; nt++) {
        int c0 = wn * 32 + nt * 8 + 2 * q;
        int d0 = mrow + g;
        float iv0 = invls[c0], iv1 = invls[c0 + 1];
        float* base0 = aout + (size_t)(qt * 64 + c0) * (NH * HD) + h * HD;
        float* base1 = aout + (size_t)(qt * 64 + c0 + 1) * (NH * HD) + h * HD;
        base0[d0]     = oacc[nt][0] * iv0;
        base1[d0]     = oacc[nt][1] * iv1;
        base0[d0 + 8] = oacc[nt][2] * iv0;
        base1[d0 + 8] = oacc[nt][3] * iv1;
    }
}

// ---------------------------------------------------------------------------
extern "C" void kernel_launch(void* const* d_in, const int* in_sizes, int n_in,
                              void* d_out, int out_size)
{
    const float* X     = (const float*)d_in[0];
    const float* cosT  = (const float*)d_in[1];
    const float* sinT  = (const float*)d_in[2];
    const float* Wq    = (const float*)d_in[4];
    const float* Wk    = (const float*)d_in[5];
    const float* Wv    = (const float*)d_in[6];
    const float* Wo    = (const float*)d_in[7];
    const float* sinks = (const float*)d_in[8];

    float* out = (float*)d_out;
    const size_t AO_ELEMS = (size_t)SEQ * HID;
    const size_t W_ELEMS  = (size_t)NH * SEQ * SEQ;
    float* wout = ((size_t)out_size >= AO_ELEMS + W_ELEMS) ? out + AO_ELEMS : nullptr;

    uint32_t *Xh, *Xl, *Wh, *Wl, *Qh, *Ql, *Kth, *Ktl, *Vth, *Vtl, *AOh, *AOl;
    float *AOd, *ILd;
    cudaGetSymbolAddress((void**)&Xh,  g_Xhi);  cudaGetSymbolAddress((void**)&Xl,  g_Xlo);
    cudaGetSymbolAddress((void**)&Wh,  g_Whi);  cudaGetSymbolAddress((void**)&Wl,  g_Wlo);
    cudaGetSymbolAddress((void**)&Qh,  g_Qhi);  cudaGetSymbolAddress((void**)&Ql,  g_Qlo);
    cudaGetSymbolAddress((void**)&Kth, g_Kthi); cudaGetSymbolAddress((void**)&Ktl, g_Ktlo);
    cudaGetSymbolAddress((void**)&Vth, g_Vthi); cudaGetSymbolAddress((void**)&Vtl, g_Vtlo);
    cudaGetSymbolAddress((void**)&AOh, g_AOhi); cudaGetSymbolAddress((void**)&AOl, g_AOlo);
    cudaGetSymbolAddress((void**)&AOd, g_AO);   cudaGetSymbolAddress((void**)&ILd, g_invl);

    const int SM128 = (128 * 132) * 4;   // 67584 B
    const int SM64  = (128 * 68) * 4;    // 34816 B
    cudaFuncSetAttribute(gemm_pk_kernel<128, 1>, cudaFuncAttributeMaxDynamicSharedMemorySize, SM128);
    cudaFuncSetAttribute(gemm_pk_kernel<128, 0>, cudaFuncAttributeMaxDynamicSharedMemorySize, SM128);
    cudaFuncSetAttribute(gemm_pk_kernel<64, 2>,  cudaFuncAttributeMaxDynamicSharedMemorySize, SM64);
    cudaFuncSetAttribute(gemm_pk_kernel<64, 3>,  cudaFuncAttributeMaxDynamicSharedMemorySize, SM64);
    cudaFuncSetAttribute(attn_kernel, cudaFuncAttributeMaxDynamicSharedMemorySize, ATTN_SMEM_BYTES);

    // ---- pack weights + X ----
    pack_rows_kernel<<<dim3(1024, 8), 256>>>(Wq, Wh + WOFF_Q, Wl + WOFF_Q, 2048);
    pack_rows_kernel<<<dim3(1024, 2), 256>>>(Wk, Wh + WOFF_K, Wl + WOFF_K, 512);
    pack_rows_kernel<<<dim3(1024, 2), 256>>>(Wv, Wh + WOFF_V, Wl + WOFF_V, 512);
    pack_rows_kernel<<<dim3(1024, 8), 256>>>(Wo, Wh + WOFF_O, Wl + WOFF_O, 2048);
    pack_cols_kernel<<<4096, 256>>>((const float4*)X, (uint2*)Xh, (uint2*)Xl);

    // ---- projections (epilogue-fused RoPE + repack) ----
    gemm_pk_kernel<128, 1><<<dim3(16, 16), 256, SM128>>>(Xh, Xl, Wh + WOFF_Q, Wl + WOFF_Q,
                                                         2048, nullptr, Qh, Ql, cosT, sinT);
    gemm_pk_kernel<64, 2><<<dim3(16, 8), 256, SM64>>>(Xh, Xl, Wh + WOFF_K, Wl + WOFF_K,
                                                      512, nullptr, Kth, Ktl, cosT, sinT);
    gemm_pk_kernel<64, 3><<<dim3(16, 8), 256, SM64>>>(Xh, Xl, Wh + WOFF_V, Wl + WOFF_V,
                                                      512, nullptr, Vth, Vtl, cosT, sinT);

    // ---- attention ----
    attn_kernel<<<dim3(SEQ / 64, NH), 256, ATTN_SMEM_BYTES>>>(Qh, Ql, Kth, Ktl, Vth, Vtl,
                                                              sinks, wout, AOd, ILd);

    // ---- finalize weights + output projection ----
    pack_cols_kernel<<<4096, 256>>>((const float4*)AOd, (uint2*)AOh, (uint2*)AOl);
    if (wout)
        finalize_weights_kernel<<<NH * SEQ, 256>>>(wout, ILd);
    gemm_pk_kernel<128, 0><<<dim3(16, 16), 256, SM128>>>(AOh, AOl, Wh + WOFF_O, Wl + WOFF_O,
                                                         2048, out, nullptr, nullptr, cosT, sinT);
}